// round 4
// baseline (speedup 1.0000x reference)
#include <cuda_runtime.h>

#define NN 100000
#define NE 1000000
#define DD 64
#define NRELTAB 401
#define BB 8

#define BM 128          // GEMM block tile rows
#define TM 8            // rows per thread
#define GEMM_THREADS 256
#define NGEMM_BLOCKS ((NN + BM - 1) / BM)       // 782
#define NPROJ_ROWS (NRELTAB + BB)               // 409
#define NPROJ_BLOCKS ((NPROJ_ROWS + 3) / 4)     // 103

#define EDGE_BLOCKS 148
#define EDGE_THREADS 1024
// dynamic smem for edge kernel: tr[401][64] + rel_emb[401][64] + tqr[8][64]
#define EDGE_SMEM ((2 * NRELTAB * DD + BB * DD) * 4)   // 207,360 bytes

// Scratch (static device globals — no runtime allocation).
__device__ __align__(256) float g_hsproj[NN * DD];   // hidden @ Ws^T
__device__ __align__(256) float g_tr[NRELTAB * DD];  // rel_emb @ Wr^T
__device__ __align__(256) float g_tqr[BB * DD];      // rel_emb[q_rel] @ Wqr^T + b
__device__ __align__(256) float g_agg[NN * DD];      // segment-sum accumulator

// ---------------------------------------------------------------------------
// Register-tiled SGEMM block: out[m][a] = sum_k in[m][k] * W[a][k]
// 128 rows x 64 cols per block, 256 threads, 8x4 per thread. FFMA-bound
// (~85% of fp32 roofline per R3 profile).
// ---------------------------------------------------------------------------
__device__ __forceinline__ void sgemm_block(float* sm,
                                            const float* __restrict__ in,
                                            const float* __restrict__ Wg,
                                            float* __restrict__ out,
                                            int M, int blockRow) {
    float* Asm = sm;            // [128][64]
    float* Wt  = sm + BM * DD;  // [64][64]  Wt[k][a]
    int t = threadIdx.x;

    for (int i = t; i < DD * DD / 4; i += GEMM_THREADS) {
        float4 w = ((const float4*)Wg)[i];
        int a = i >> 4, k = (i & 15) * 4;
        Wt[(k + 0) * DD + a] = w.x;
        Wt[(k + 1) * DD + a] = w.y;
        Wt[(k + 2) * DD + a] = w.z;
        Wt[(k + 3) * DD + a] = w.w;
    }
    int row0 = blockRow * BM;
    for (int i = t; i < BM * DD / 4; i += GEMM_THREADS) {
        int m = i >> 4;
        float4 v = make_float4(0.f, 0.f, 0.f, 0.f);
        if (row0 + m < M)
            v = ((const float4*)(in + (size_t)(row0 + m) * DD))[i & 15];
        ((float4*)Asm)[i] = v;
    }
    __syncthreads();

    int rt = t >> 4, ct = t & 15;
    const float* arow = Asm + rt * TM * DD;
    const float4* wt4 = (const float4*)Wt + ct;

    float4 acc[TM];
#pragma unroll
    for (int r = 0; r < TM; r++) acc[r] = make_float4(0.f, 0.f, 0.f, 0.f);

#pragma unroll 8
    for (int k = 0; k < DD; k++) {
        float4 w = wt4[k * 16];
#pragma unroll
        for (int r = 0; r < TM; r++) {
            float a = arow[r * DD + k];
            acc[r].x = fmaf(a, w.x, acc[r].x);
            acc[r].y = fmaf(a, w.y, acc[r].y);
            acc[r].z = fmaf(a, w.z, acc[r].z);
            acc[r].w = fmaf(a, w.w, acc[r].w);
        }
    }

#pragma unroll
    for (int r = 0; r < TM; r++) {
        int m = row0 + rt * TM + r;
        if (m < M) ((float4*)(out + (size_t)m * DD))[ct] = acc[r];
    }
}

// ---------------------------------------------------------------------------
// Fused front kernel: zero g_agg + hsproj SGEMM tiles + relation projections.
// ---------------------------------------------------------------------------
__global__ __launch_bounds__(GEMM_THREADS)
void fused_pre_kernel(const float* __restrict__ hidden,
                      const float* __restrict__ Ws,
                      const float* __restrict__ emb,
                      const float* __restrict__ Wr,
                      const float* __restrict__ Wqr,
                      const float* __restrict__ bias,
                      const int* __restrict__ qrel) {
    __shared__ float sm[BM * DD + DD * DD];  // 48KB, reused by both paths
    int t = threadIdx.x;

    if (blockIdx.x < NGEMM_BLOCKS) {
        {
            int i = blockIdx.x * GEMM_THREADS + t;
            int stride = NGEMM_BLOCKS * GEMM_THREADS;
            float4* p = (float4*)g_agg;
            const int n4 = NN * DD / 4;
            for (int j = i; j < n4; j += stride)
                p[j] = make_float4(0.f, 0.f, 0.f, 0.f);
        }
        sgemm_block(sm, hidden, Ws, g_hsproj, NN, blockIdx.x);
        return;
    }

    // ---- relation projection path: 4 rows per block, 64 threads per row ----
    float* WrS  = sm;               // [64][65] padded
    float* WqrS = sm + DD * 65;     // [64][65] padded
    float* rows = sm + 2 * DD * 65; // [4][64]
    for (int i = t; i < DD * DD; i += GEMM_THREADS) {
        WrS [(i >> 6) * 65 + (i & 63)] = Wr[i];
        WqrS[(i >> 6) * 65 + (i & 63)] = Wqr[i];
    }
    int sub = t >> 6, a = t & 63;
    int rid = (blockIdx.x - NGEMM_BLOCKS) * 4 + sub;
    bool valid = rid < NPROJ_ROWS;
    bool is_qr = rid >= NRELTAB;
    int r = is_qr ? (rid - NRELTAB) : rid;
    int src = valid ? (is_qr ? qrel[r] : r) : 0;
    rows[sub * DD + a] = emb[src * DD + a];
    __syncthreads();
    if (!valid) return;

    const float* W = is_qr ? WqrS : WrS;
    const float* rw = rows + sub * DD;
    float acc = is_qr ? bias[a] : 0.f;
#pragma unroll
    for (int k = 0; k < DD; k++) acc = fmaf(rw[k], W[a * 65 + k], acc);
    (is_qr ? g_tqr : g_tr)[r * DD + a] = acc;
}

__global__ __launch_bounds__(GEMM_THREADS)
void gemm_out_kernel(const float* __restrict__ Wh, float* __restrict__ out) {
    __shared__ float sm[BM * DD + DD * DD];
    sgemm_block(sm, g_agg, Wh, out, NN, blockIdx.x);
}

// ---------------------------------------------------------------------------
// Persistent edge kernel. The L2-byte model (R3): 1.3KB/edge -> 90us at the
// LTS cap. Staging tr + rel_emb + tqr in smem removes ~512B/edge of L2
// traffic (those gathers become LDS); remaining L2 per edge:
// hsp 256 + hs 256 + idx 24 + RED 256 ~= 800B -> ~65us target.
// 16 lanes/edge, float4 per lane, red.global.add.v4.f32 scatter.
// ---------------------------------------------------------------------------
__global__ __launch_bounds__(EDGE_THREADS, 1)
void edge_kernel(const int* __restrict__ edges,
                 const float* __restrict__ hidden,
                 const float* __restrict__ rel_emb,
                 const float* __restrict__ walpha_w,
                 const float* __restrict__ walpha_b) {
    extern __shared__ float sm[];
    float* s_tr  = sm;                     // [401*64]
    float* s_re  = sm + NRELTAB * DD;      // [401*64]
    float* s_tqr = sm + 2 * NRELTAB * DD;  // [8*64]

    // cooperative smem fill (float4)
    const int n4 = NRELTAB * DD / 4;  // 6416
    for (int i = threadIdx.x; i < n4; i += EDGE_THREADS) {
        ((float4*)s_tr)[i] = ((const float4*)g_tr)[i];
        ((float4*)s_re)[i] = ((const float4*)rel_emb)[i];
    }
    if (threadIdx.x < BB * DD / 4)
        ((float4*)s_tqr)[threadIdx.x] = ((const float4*)g_tqr)[threadIdx.x];
    __syncthreads();

    const int l = threadIdx.x & 15;
    const int c = l * 4;
    const float4 wv = __ldg((const float4*)walpha_w + l);
    const float wb = __ldg(walpha_b);
    // shfl mask: just this 16-lane half of the warp (trip counts can differ
    // across halves at the grid-stride boundary)
    const unsigned hmask = 0xFFFFu << (threadIdx.x & 16);

    unsigned group  = blockIdx.x * (EDGE_THREADS / 16) + (threadIdx.x >> 4);
    unsigned stride = EDGE_BLOCKS * (EDGE_THREADS / 16);

    for (unsigned eid = group; eid < NE; eid += stride) {
        const int* e = edges + (size_t)eid * 6;
        int r_idx = __ldg(e + 0);
        int rel   = __ldg(e + 2);
        int sub   = __ldg(e + 4);
        int obj   = __ldg(e + 5);

        float4 hsp = __ldg((const float4*)(g_hsproj + (size_t)sub * DD + c));
        float4 hs  = __ldg((const float4*)(hidden + (size_t)sub * DD + c));
        float4 tr  = *(const float4*)(s_tr + rel * DD + c);
        float4 hr  = *(const float4*)(s_re + rel * DD + c);
        float4 tq  = *(const float4*)(s_tqr + r_idx * DD + c);

        float p0 = fmaxf(hsp.x + tr.x + tq.x, 0.f);
        float p1 = fmaxf(hsp.y + tr.y + tq.y, 0.f);
        float p2 = fmaxf(hsp.z + tr.z + tq.z, 0.f);
        float p3 = fmaxf(hsp.w + tr.w + tq.w, 0.f);
        float part = fmaf(p0, wv.x, fmaf(p1, wv.y, fmaf(p2, wv.z, p3 * wv.w)));
#pragma unroll
        for (int o = 8; o > 0; o >>= 1)
            part += __shfl_xor_sync(hmask, part, o);

        float alpha = 1.f / (1.f + __expf(-(part + wb)));

        float m0 = alpha * (hs.x + hr.x);
        float m1 = alpha * (hs.y + hr.y);
        float m2 = alpha * (hs.z + hr.z);
        float m3 = alpha * (hs.w + hr.w);

        float* dst = g_agg + (size_t)obj * DD + c;
        asm volatile("red.global.add.v4.f32 [%0], {%1, %2, %3, %4};"
                     :: "l"(dst), "f"(m0), "f"(m1), "f"(m2), "f"(m3)
                     : "memory");
    }
}

// ---------------------------------------------------------------------------
// Inputs (metadata order):
//  0 q_sub[8] i32, 1 q_rel[8] i32, 2 hidden[100000,64] f32, 3 edges[1000000,6] i32,
//  4 nodes[100000,2] i32, 5 old_nodes_new_idx[50000] i32, 6 batchsize i32,
//  7 rel_emb[401,64] f32, 8 Ws[64,64], 9 Wr[64,64], 10 Wqr_w[64,64], 11 Wqr_b[64],
// 12 walpha_w[1,64], 13 walpha_b[1], 14 Wh[64,64]
// Output: hidden_new[100000,64] f32
// ---------------------------------------------------------------------------
extern "C" void kernel_launch(void* const* d_in, const int* in_sizes, int n_in,
                              void* d_out, int out_size) {
    const int*   q_rel    = (const int*)d_in[1];
    const float* hidden   = (const float*)d_in[2];
    const int*   edges    = (const int*)d_in[3];
    const float* rel_emb  = (const float*)d_in[7];
    const float* Ws       = (const float*)d_in[8];
    const float* Wr       = (const float*)d_in[9];
    const float* Wqr_w    = (const float*)d_in[10];
    const float* Wqr_b    = (const float*)d_in[11];
    const float* walpha_w = (const float*)d_in[12];
    const float* walpha_b = (const float*)d_in[13];
    const float* Wh       = (const float*)d_in[14];
    float* out = (float*)d_out;

    // raise dynamic smem cap for the persistent edge kernel (host-side call,
    // not a stream op; idempotent, no allocation)
    cudaFuncSetAttribute(edge_kernel,
                         cudaFuncAttributeMaxDynamicSharedMemorySize, EDGE_SMEM);

    fused_pre_kernel<<<NGEMM_BLOCKS + NPROJ_BLOCKS, GEMM_THREADS>>>(
        hidden, Ws, rel_emb, Wr, Wqr_w, Wqr_b, q_rel);
    edge_kernel<<<EDGE_BLOCKS, EDGE_THREADS, EDGE_SMEM>>>(
        edges, hidden, rel_emb, walpha_w, walpha_b);
    gemm_out_kernel<<<NGEMM_BLOCKS, GEMM_THREADS>>>(Wh, out);
}

// round 5
// speedup vs baseline: 1.1071x; 1.1071x over previous
#include <cuda_runtime.h>
#include <cuda_fp16.h>

#define NN 100000
#define NE 1000000
#define DD 64
#define NRELTAB 401
#define BB 8

#define BM 128
#define TM 8
#define GEMM_THREADS 256
#define NGEMM_BLOCKS ((NN + BM - 1) / BM)        // 782
#define NPROJ_ROWS (2 * NRELTAB + BB)            // 810: Wr rows, Wh rows, Wqr rows
#define NPROJ_BLOCKS ((NPROJ_ROWS + 3) / 4)      // 203
// dynamic smem for fused_pre: max(GEMM path 64KB, proj path ~51KB)
#define PRE_SMEM ((BM * DD + 2 * DD * DD) * 4 + 1024)

// Scratch (static device globals — no runtime allocation).
__device__ __align__(256) __half g_hsp16[NN * DD];  // fp16(hidden @ Ws^T)
__device__ __align__(256) __half g_hp216[NN * DD];  // fp16(hidden @ Wh^T)
__device__ __align__(256) float g_tr[NRELTAB * DD];   // rel_emb @ Wr^T
__device__ __align__(256) float g_rp2[NRELTAB * DD];  // rel_emb @ Wh^T
__device__ __align__(256) float g_tqr[BB * DD];       // rel_emb[q_rel] @ Wqr^T + b

// ---------------------------------------------------------------------------
// Fused front kernel.
//  blocks [0, NGEMM_BLOCKS): zero d_out slice + dual-output SGEMM tile:
//     hsp16 = fp16(hidden @ Ws^T), hp216 = fp16(hidden @ Wh^T)
//     (one shared A tile, two weight tiles -> 2x FMA per A byte; the R3/R4
//      profile showed fma pipe only 27.6% busy, so the extra FMA is ~free)
//  blocks [NGEMM_BLOCKS, +NPROJ_BLOCKS): relation projections, 4 rows/block:
//     rid in [0,401)    : g_tr[rid]  = rel_emb[rid] @ Wr^T
//     rid in [401,802)  : g_rp2[rid-401] = rel_emb[rid-401] @ Wh^T
//     rid in [802,810)  : g_tqr[rid-802] = rel_emb[q_rel[.]] @ Wqr^T + bias
// ---------------------------------------------------------------------------
__global__ __launch_bounds__(GEMM_THREADS)
void fused_pre_kernel(const float* __restrict__ hidden,
                      const float* __restrict__ Ws,
                      const float* __restrict__ Wh,
                      const float* __restrict__ emb,
                      const float* __restrict__ Wr,
                      const float* __restrict__ Wqr,
                      const float* __restrict__ bias,
                      const int* __restrict__ qrel,
                      float* __restrict__ out) {
    extern __shared__ float sm[];
    int t = threadIdx.x;

    if (blockIdx.x < NGEMM_BLOCKS) {
        // zero the output buffer (edge kernel REDs into it)
        {
            int i = blockIdx.x * GEMM_THREADS + t;
            int stride = NGEMM_BLOCKS * GEMM_THREADS;
            float4* p = (float4*)out;
            const int n4 = NN * DD / 4;
            for (int j = i; j < n4; j += stride)
                p[j] = make_float4(0.f, 0.f, 0.f, 0.f);
        }

        float* Asm = sm;                 // [128][64]
        float* Wt1 = sm + BM * DD;       // Ws^T as [k][a]
        float* Wt2 = Wt1 + DD * DD;      // Wh^T as [k][a]

        for (int i = t; i < DD * DD / 4; i += GEMM_THREADS) {
            int a = i >> 4, k = (i & 15) * 4;
            float4 w = ((const float4*)Ws)[i];
            Wt1[(k + 0) * DD + a] = w.x; Wt1[(k + 1) * DD + a] = w.y;
            Wt1[(k + 2) * DD + a] = w.z; Wt1[(k + 3) * DD + a] = w.w;
            float4 v = ((const float4*)Wh)[i];
            Wt2[(k + 0) * DD + a] = v.x; Wt2[(k + 1) * DD + a] = v.y;
            Wt2[(k + 2) * DD + a] = v.z; Wt2[(k + 3) * DD + a] = v.w;
        }
        int row0 = blockIdx.x * BM;
        for (int i = t; i < BM * DD / 4; i += GEMM_THREADS) {
            int m = i >> 4;
            float4 v = make_float4(0.f, 0.f, 0.f, 0.f);
            if (row0 + m < NN)
                v = ((const float4*)(hidden + (size_t)(row0 + m) * DD))[i & 15];
            ((float4*)Asm)[i] = v;
        }
        __syncthreads();

        int rt = t >> 4, ct = t & 15;
        const float* arow = Asm + rt * TM * DD;
        const float4* w1p = (const float4*)Wt1 + ct;
        const float4* w2p = (const float4*)Wt2 + ct;

        float4 acc1[TM], acc2[TM];
#pragma unroll
        for (int r = 0; r < TM; r++) {
            acc1[r] = make_float4(0.f, 0.f, 0.f, 0.f);
            acc2[r] = make_float4(0.f, 0.f, 0.f, 0.f);
        }

#pragma unroll 4
        for (int k = 0; k < DD; k++) {
            float4 w1 = w1p[k * 16];
            float4 w2 = w2p[k * 16];
#pragma unroll
            for (int r = 0; r < TM; r++) {
                float a = arow[r * DD + k];
                acc1[r].x = fmaf(a, w1.x, acc1[r].x);
                acc1[r].y = fmaf(a, w1.y, acc1[r].y);
                acc1[r].z = fmaf(a, w1.z, acc1[r].z);
                acc1[r].w = fmaf(a, w1.w, acc1[r].w);
                acc2[r].x = fmaf(a, w2.x, acc2[r].x);
                acc2[r].y = fmaf(a, w2.y, acc2[r].y);
                acc2[r].z = fmaf(a, w2.z, acc2[r].z);
                acc2[r].w = fmaf(a, w2.w, acc2[r].w);
            }
        }

#pragma unroll
        for (int r = 0; r < TM; r++) {
            int m = row0 + rt * TM + r;
            if (m < NN) {
                uint2 h1, h2;
                ((__half2*)&h1)[0] = __floats2half2_rn(acc1[r].x, acc1[r].y);
                ((__half2*)&h1)[1] = __floats2half2_rn(acc1[r].z, acc1[r].w);
                ((__half2*)&h2)[0] = __floats2half2_rn(acc2[r].x, acc2[r].y);
                ((__half2*)&h2)[1] = __floats2half2_rn(acc2[r].z, acc2[r].w);
                ((uint2*)(g_hsp16 + (size_t)m * DD))[ct] = h1;
                ((uint2*)(g_hp216 + (size_t)m * DD))[ct] = h2;
            }
        }
        return;
    }

    // ---- relation projection path: 4 rows/block, 64 threads per row ----
    float* WrS  = sm;               // [64][65]
    float* WhS  = sm + DD * 65;     // [64][65]
    float* WqrS = sm + 2 * DD * 65; // [64][65]
    float* rows = sm + 3 * DD * 65; // [4][64]
    for (int i = t; i < DD * DD; i += GEMM_THREADS) {
        int r = i >> 6, c = i & 63;
        WrS [r * 65 + c] = Wr[i];
        WhS [r * 65 + c] = Wh[i];
        WqrS[r * 65 + c] = Wqr[i];
    }
    int sub = t >> 6, a = t & 63;
    int rid = (blockIdx.x - NGEMM_BLOCKS) * 4 + sub;
    bool valid = rid < NPROJ_ROWS;
    int seg = valid ? ((rid >= 2 * NRELTAB) ? 2 : (rid >= NRELTAB) ? 1 : 0) : 0;
    int r = rid - (seg == 2 ? 2 * NRELTAB : seg == 1 ? NRELTAB : 0);
    int src = valid ? (seg == 2 ? qrel[r] : r) : 0;
    rows[sub * DD + a] = emb[src * DD + a];
    __syncthreads();
    if (!valid) return;

    const float* W = (seg == 2) ? WqrS : (seg == 1) ? WhS : WrS;
    const float* rw = rows + sub * DD;
    float acc = (seg == 2) ? bias[a] : 0.f;
#pragma unroll
    for (int k = 0; k < DD; k++) acc = fmaf(rw[k], W[a * 65 + k], acc);
    float* dstt = (seg == 2) ? g_tqr : (seg == 1) ? g_rp2 : g_tr;
    dstt[r * DD + a] = acc;
}

// ---------------------------------------------------------------------------
// Edge kernel (R3 shape: 256-thread blocks, 16 lanes/edge, full L1).
//   alpha = sigmoid( dot(relu(hsp16[sub] + tr[rel] + tqr[r_idx]), w) + b )
//   red.global.add.v4.f32 of alpha*(hp216[sub] + rp2[rel]) directly into OUT
// Gathers are fp16 (128B/row instead of 256B); tables stay fp32 via __ldg
// (hot in L1/L2). Index loads: 4 lanes load, shfl-broadcast to the group.
// ---------------------------------------------------------------------------
__global__ __launch_bounds__(256)
void edge_kernel(const int* __restrict__ edges,
                 const float* __restrict__ walpha_w,
                 const float* __restrict__ walpha_b,
                 float* __restrict__ out) {
    unsigned gtid = blockIdx.x * blockDim.x + threadIdx.x;
    unsigned eid = gtid >> 4;  // exact: grid covers NE
    int l = gtid & 15;

    // lane-split index load + broadcast (cols 0,2,4,5 of the 6-int row)
    const int* e = edges + (size_t)eid * 6;
    int v = 0;
    if (l < 4) v = __ldg(e + ((0x5420u >> (l * 4)) & 0xF));  // 0,2,4,5
    int r_idx = __shfl_sync(0xffffffffu, v, 0, 16);
    int rel   = __shfl_sync(0xffffffffu, v, 1, 16);
    int sub   = __shfl_sync(0xffffffffu, v, 2, 16);
    int obj   = __shfl_sync(0xffffffffu, v, 3, 16);

    int c = l * 4;
    uint2 ha = __ldg((const uint2*)(g_hsp16 + (size_t)sub * DD + c));
    uint2 hb = __ldg((const uint2*)(g_hp216 + (size_t)sub * DD + c));
    float2 a0 = __half22float2(*(const __half2*)&ha.x);
    float2 a1 = __half22float2(*(const __half2*)&ha.y);
    float2 b0 = __half22float2(*(const __half2*)&hb.x);
    float2 b1 = __half22float2(*(const __half2*)&hb.y);

    float4 tr = __ldg((const float4*)(g_tr + rel * DD + c));
    float4 tq = __ldg((const float4*)(g_tqr + r_idx * DD + c));
    float4 rp = __ldg((const float4*)(g_rp2 + rel * DD + c));
    float4 wv = __ldg((const float4*)walpha_w + l);

    float p0 = fmaxf(a0.x + tr.x + tq.x, 0.f);
    float p1 = fmaxf(a0.y + tr.y + tq.y, 0.f);
    float p2 = fmaxf(a1.x + tr.z + tq.z, 0.f);
    float p3 = fmaxf(a1.y + tr.w + tq.w, 0.f);
    float part = fmaf(p0, wv.x, fmaf(p1, wv.y, fmaf(p2, wv.z, p3 * wv.w)));
#pragma unroll
    for (int o = 8; o > 0; o >>= 1)
        part += __shfl_xor_sync(0xffffffffu, part, o);

    float alpha = 1.f / (1.f + __expf(-(part + __ldg(walpha_b))));

    float m0 = alpha * (b0.x + rp.x);
    float m1 = alpha * (b0.y + rp.y);
    float m2 = alpha * (b1.x + rp.z);
    float m3 = alpha * (b1.y + rp.w);

    float* dst = out + (size_t)obj * DD + c;
    asm volatile("red.global.add.v4.f32 [%0], {%1, %2, %3, %4};"
                 :: "l"(dst), "f"(m0), "f"(m1), "f"(m2), "f"(m3)
                 : "memory");
}

// ---------------------------------------------------------------------------
// Inputs (metadata order):
//  0 q_sub[8] i32, 1 q_rel[8] i32, 2 hidden[100000,64] f32, 3 edges[1000000,6] i32,
//  4 nodes[100000,2] i32, 5 old_nodes_new_idx[50000] i32, 6 batchsize i32,
//  7 rel_emb[401,64] f32, 8 Ws[64,64], 9 Wr[64,64], 10 Wqr_w[64,64], 11 Wqr_b[64],
// 12 walpha_w[1,64], 13 walpha_b[1], 14 Wh[64,64]
// Output: hidden_new[100000,64] f32
// ---------------------------------------------------------------------------
extern "C" void kernel_launch(void* const* d_in, const int* in_sizes, int n_in,
                              void* d_out, int out_size) {
    const int*   q_rel    = (const int*)d_in[1];
    const float* hidden   = (const float*)d_in[2];
    const int*   edges    = (const int*)d_in[3];
    const float* rel_emb  = (const float*)d_in[7];
    const float* Ws       = (const float*)d_in[8];
    const float* Wr       = (const float*)d_in[9];
    const float* Wqr_w    = (const float*)d_in[10];
    const float* Wqr_b    = (const float*)d_in[11];
    const float* walpha_w = (const float*)d_in[12];
    const float* walpha_b = (const float*)d_in[13];
    const float* Wh       = (const float*)d_in[14];
    float* out = (float*)d_out;

    cudaFuncSetAttribute(fused_pre_kernel,
                         cudaFuncAttributeMaxDynamicSharedMemorySize, PRE_SMEM);

    fused_pre_kernel<<<NGEMM_BLOCKS + NPROJ_BLOCKS, GEMM_THREADS, PRE_SMEM>>>(
        hidden, Ws, Wh, rel_emb, Wr, Wqr_w, Wqr_b, q_rel, out);
    edge_kernel<<<NE / 16, 256>>>(edges, walpha_w, walpha_b, out);
}